// round 3
// baseline (speedup 1.0000x reference)
#include <cuda_runtime.h>
#include <math.h>
#include <stdint.h>

#define Gn 8
#define Hn 64
#define In 64
#define Bn 32
#define Tn 1000
#define ROWS (Bn * Tn)   // 32000

// Scratch: xp[((b*G+g)*T + t)*192 + j]  — sequential in t per (b,g)
__device__ float g_xp[(size_t)Bn * Gn * Tn * 192];

// ---------------- packed f32x2 helpers (sm_103a) ----------------
__device__ __forceinline__ uint64_t ffma2(uint64_t a, uint64_t b, uint64_t c) {
    uint64_t d;
    asm("fma.rn.f32x2 %0, %1, %2, %3;" : "=l"(d) : "l"(a), "l"(b), "l"(c));
    return d;
}
__device__ __forceinline__ uint64_t fadd2(uint64_t a, uint64_t b) {
    uint64_t d;
    asm("add.rn.f32x2 %0, %1, %2;" : "=l"(d) : "l"(a), "l"(b));
    return d;
}
__device__ __forceinline__ uint64_t pack2(float lo, float hi) {
    uint64_t d;
    asm("mov.b64 %0, {%1, %2};" : "=l"(d) : "f"(lo), "f"(hi));
    return d;
}
__device__ __forceinline__ float2 unpack2(uint64_t v) {
    float lo, hi;
    asm("mov.b64 {%0, %1}, %2;" : "=f"(lo), "=f"(hi) : "l"(v));
    return make_float2(lo, hi);
}
__device__ __forceinline__ float fsig(float x) {
    return __fdividef(1.f, 1.f + __expf(-x));
}

// ---------------------------------------------------------------------------
// Phase 1: xp = x @ Wih^T + bih  (per group; 64-row x 64-col tiles, f32x2)
// grid = (500, 8, 3), block = 256
// ---------------------------------------------------------------------------
__global__ void __launch_bounds__(256) xproj_kernel(const float* __restrict__ x,
                                                    const float* __restrict__ Wih,
                                                    const float* __restrict__ bih)
{
    __shared__ __align__(16) float xs[64][68];  // [k][row]
    __shared__ __align__(16) float ws[64][68];  // [k][col]

    const int tile = blockIdx.x;
    const int g    = blockIdx.y;
    const int sec  = blockIdx.z;
    const int tid  = threadIdx.x;

    for (int idx = tid; idx < 64 * 16; idx += 256) {
        int row = idx >> 4;
        int k4  = (idx & 15) * 4;
        int n   = tile * 64 + row;
        float4 v = *(const float4*)&x[(size_t)n * (Gn * In) + g * In + k4];
        xs[k4 + 0][row] = v.x;
        xs[k4 + 1][row] = v.y;
        xs[k4 + 2][row] = v.z;
        xs[k4 + 3][row] = v.w;
    }
    for (int idx = tid; idx < 64 * 16; idx += 256) {
        int j  = idx >> 4;
        int k4 = (idx & 15) * 4;
        float4 v = *(const float4*)&Wih[((size_t)g * 192 + sec * 64 + j) * In + k4];
        ws[k4 + 0][j] = v.x;
        ws[k4 + 1][j] = v.y;
        ws[k4 + 2][j] = v.z;
        ws[k4 + 3][j] = v.w;
    }
    __syncthreads();

    const int tx = tid & 15;
    const int ty = tid >> 4;
    const int r0 = ty * 4;
    const int c0 = tx * 4;

    uint64_t A01[4], A23[4];
#pragma unroll
    for (int i = 0; i < 4; i++) { A01[i] = 0ull; A23[i] = 0ull; }

#pragma unroll 8
    for (int k = 0; k < 64; k++) {
        float4 av = *(const float4*)&xs[k][r0];
        ulonglong2 wv = *(const ulonglong2*)&ws[k][c0];
        uint64_t a0 = pack2(av.x, av.x);
        uint64_t a1 = pack2(av.y, av.y);
        uint64_t a2 = pack2(av.z, av.z);
        uint64_t a3 = pack2(av.w, av.w);
        A01[0] = ffma2(a0, wv.x, A01[0]);  A23[0] = ffma2(a0, wv.y, A23[0]);
        A01[1] = ffma2(a1, wv.x, A01[1]);  A23[1] = ffma2(a1, wv.y, A23[1]);
        A01[2] = ffma2(a2, wv.x, A01[2]);  A23[2] = ffma2(a2, wv.y, A23[2]);
        A01[3] = ffma2(a3, wv.x, A01[3]);  A23[3] = ffma2(a3, wv.y, A23[3]);
    }

    float4 bv = *(const float4*)&bih[g * 192 + sec * 64 + c0];
#pragma unroll
    for (int i = 0; i < 4; i++) {
        int n = tile * 64 + r0 + i;
        int b = n / Tn;
        int t = n - b * Tn;
        size_t o = ((size_t)(b * Gn + g) * Tn + t) * 192 + sec * 64 + c0;
        float2 lo = unpack2(A01[i]);
        float2 hi = unpack2(A23[i]);
        float4 v;
        v.x = lo.x + bv.x;
        v.y = lo.y + bv.y;
        v.z = hi.x + bv.z;
        v.w = hi.y + bv.w;
        *(float4*)&g_xp[o] = v;
    }
}

// ---------------------------------------------------------------------------
// Phase 2: sequential scan. One block per (b-pair, g): handles b0=2bx, b1=2bx+1.
// 192 threads: thread j owns gate-row j of Whh (shared across both b's).
// Gate phase: threads 0..127 each finish one (pair, h-index).
// grid = (16, 8), block = 192
// ---------------------------------------------------------------------------
__global__ void __launch_bounds__(192) scan_kernel(const float* __restrict__ h0,
                                                   const float* __restrict__ Whh,
                                                   const float* __restrict__ bhh,
                                                   float* __restrict__ out)
{
    const int bx = blockIdx.x;
    const int g  = blockIdx.y;
    const int b0 = 2 * bx;
    const int b1 = b0 + 1;
    const int j  = threadIdx.x;

    __shared__ __align__(16) float hA[64];
    __shared__ __align__(16) float hB[64];
    __shared__ __align__(16) float ghA[192];
    __shared__ __align__(16) float ghB[192];

    // Whh row j as 16 packed-pair registers (shared by both batch elements)
    ulonglong2 w[16];
    const ulonglong2* wrow = (const ulonglong2*)&Whh[((size_t)g * 192 + j) * Hn];
#pragma unroll
    for (int q = 0; q < 16; q++) w[q] = wrow[q];
    const float bj = bhh[g * 192 + j];

    if (j < 64) {
        hA[j] = h0[((size_t)g * Bn + b0) * Hn + j];
        hB[j] = h0[((size_t)g * Bn + b1) * Hn + j];
    }

    // gate-thread setup: sel picks pair, k is the h index
    const int  sel     = j >> 6;          // 0 -> pair A(b0), 1 -> pair B(b1)
    const int  k       = j & 63;
    const bool is_gate = (j < 128);
    const int  bsel    = sel ? b1 : b0;

    const float* xb   = &g_xp[((size_t)(bsel * Gn + g) * Tn) * 192 + k];
    float*       outp = out + (size_t)bsel * Tn * (Gn * Hn) + g * Hn + k;
    float*       hS   = sel ? hB : hA;
    const float* ghS  = sel ? ghB : ghA;

    // 2-deep prefetch ring for (xr, xz, xn)
    float xr0 = 0.f, xz0 = 0.f, xn0 = 0.f, xr1 = 0.f, xz1 = 0.f, xn1 = 0.f;
    if (is_gate) {
        xr0 = __ldcs(xb + 0);   xz0 = __ldcs(xb + 64);        xn0 = __ldcs(xb + 128);
        xr1 = __ldcs(xb + 192); xz1 = __ldcs(xb + 192 + 64);  xn1 = __ldcs(xb + 192 + 128);
    }

#define STEP(T_, XR_, XZ_, XN_)                                               \
    {                                                                         \
        __syncthreads();                                                      \
        uint64_t A0 = pack2(bj, 0.f), A1 = 0ull, A2 = 0ull, A3 = 0ull;        \
        uint64_t B0 = pack2(bj, 0.f), B1 = 0ull, B2 = 0ull, B3 = 0ull;        \
        const ulonglong2* h2A = (const ulonglong2*)hA;                        \
        const ulonglong2* h2B = (const ulonglong2*)hB;                        \
        _Pragma("unroll")                                                     \
        for (int q = 0; q < 16; q += 2) {                                     \
            ulonglong2 ha = h2A[q];                                           \
            ulonglong2 hb = h2A[q + 1];                                       \
            ulonglong2 hc = h2B[q];                                           \
            ulonglong2 hd = h2B[q + 1];                                       \
            A0 = ffma2(w[q].x,     ha.x, A0);                                 \
            A1 = ffma2(w[q].y,     ha.y, A1);                                 \
            A2 = ffma2(w[q + 1].x, hb.x, A2);                                 \
            A3 = ffma2(w[q + 1].y, hb.y, A3);                                 \
            B0 = ffma2(w[q].x,     hc.x, B0);                                 \
            B1 = ffma2(w[q].y,     hc.y, B1);                                 \
            B2 = ffma2(w[q + 1].x, hd.x, B2);                                 \
            B3 = ffma2(w[q + 1].y, hd.y, B3);                                 \
        }                                                                     \
        float2 sA = unpack2(fadd2(fadd2(A0, A1), fadd2(A2, A3)));             \
        float2 sB = unpack2(fadd2(fadd2(B0, B1), fadd2(B2, B3)));             \
        ghA[j] = sA.x + sA.y;                                                 \
        ghB[j] = sB.x + sB.y;                                                 \
        __syncthreads();                                                      \
        if (is_gate) {                                                        \
            float hprev = hS[k];                                              \
            float rr = fsig((XR_) + ghS[k]);                                  \
            float zz = fsig((XZ_) + ghS[64 + k]);                             \
            float aa = (XN_) + rr * ghS[128 + k];                             \
            float nn = __fmaf_rn(2.f, fsig(2.f * aa), -1.f);                  \
            float hn = nn + zz * (hprev - nn);                                \
            hS[k] = hn;                                                       \
            __stcs(&outp[(size_t)(T_) * (Gn * Hn)], hn);                      \
        }                                                                     \
    }

    for (int t = 0; t < Tn; t += 2) {
        STEP(t, xr0, xz0, xn0);
        if (is_gate) {
            size_t o = (size_t)min(t + 2, Tn - 1) * 192;
            xr0 = __ldcs(xb + o); xz0 = __ldcs(xb + o + 64); xn0 = __ldcs(xb + o + 128);
        }
        STEP(t + 1, xr1, xz1, xn1);
        if (is_gate) {
            size_t o = (size_t)min(t + 3, Tn - 1) * 192;
            xr1 = __ldcs(xb + o); xz1 = __ldcs(xb + o + 64); xn1 = __ldcs(xb + o + 128);
        }
    }
#undef STEP

    __syncthreads();
    if (j < 64) {
        size_t base = (size_t)Bn * Tn * (Gn * Hn);
        out[base + ((size_t)g * Bn + b0) * Hn + j] = hA[j];
        out[base + ((size_t)g * Bn + b1) * Hn + j] = hB[j];
    }
}

// ---------------------------------------------------------------------------
extern "C" void kernel_launch(void* const* d_in, const int* in_sizes, int n_in,
                              void* d_out, int out_size)
{
    const float* x   = (const float*)d_in[0];
    const float* h0  = (const float*)d_in[1];
    const float* Wih = (const float*)d_in[2];
    const float* Whh = (const float*)d_in[3];
    const float* bih = (const float*)d_in[4];
    const float* bhh = (const float*)d_in[5];
    float* out = (float*)d_out;

    dim3 g1(ROWS / 64, Gn, 3);
    xproj_kernel<<<g1, 256>>>(x, Wih, bih);

    dim3 g2(Bn / 2, Gn);
    scan_kernel<<<g2, 192>>>(h0, Whh, bhh, out);
}